// round 13
// baseline (speedup 1.0000x reference)
#include <cuda_runtime.h>
#include <cstdint>

#define BATCH 4
#define NSEQ  512
#define N_TOK (BATCH * NSEQ)   // 2048
#define D     64

// Scratch (allocation-free rule: __device__ globals)
__device__ __align__(256) float    g_a[N_TOK * D];   // a = emb @ W1[:64] + b1
__device__ __align__(256) float    g_b[N_TOK * D];   // b = emb @ W1[64:]
// Per-lane tf32 B-fragments of W2 for mma.m16n8k8:
//   g_wlo[s][lane][q]: q = nb*2+r for nb=0,1 ; g_whi: nb=2,3
//   value = tf32( W2[ 8s + (lane&3) + 4r ][ 8nb + (lane>>2) ] )
__device__ __align__(256) uint32_t g_wlo[8 * 32 * 4];
__device__ __align__(256) uint32_t g_whi[8 * 32 * 4];

// ---------------------------------------------------------------------------
// Phase 1: per-token chain + W2 fragment repack
// ---------------------------------------------------------------------------
__global__ void precompute_kernel(
    const float* __restrict__ x,
    const float* __restrict__ Wf,  const float* __restrict__ bf,
    const float* __restrict__ Wp1, const float* __restrict__ bp1,
    const float* __restrict__ Wp2, const float* __restrict__ bp2,
    const float* __restrict__ Wn,  const float* __restrict__ bn,
    const float* __restrict__ W1,  const float* __restrict__ b1,
    const float* __restrict__ W2)
{
    __shared__ float s_x [4][16];
    __shared__ float s_h [4][D];
    __shared__ float s_h2[4][D];

    const int tl = threadIdx.x >> 6;
    const int d  = threadIdx.x & 63;
    const int t  = blockIdx.x * 4 + tl;

    if (blockIdx.x == 0) {
        // W2 [k=64][n=32] -> per-lane mma B fragments (tf32)
        for (int idx = threadIdx.x; idx < 2048; idx += 256) {
            int s  = idx >> 8;          // k-step 0..7
            int l  = (idx >> 3) & 31;   // lane
            int q  = idx & 7;           // 0..7
            int nb = q >> 1;            // n-block 0..3
            int r  = q & 1;             // b-reg 0..1
            int gid = l >> 2, t4 = l & 3;
            int k = 8 * s + t4 + 4 * r;
            int n = 8 * nb + gid;
            uint32_t tv;
            asm("cvt.rna.tf32.f32 %0, %1;" : "=r"(tv) : "f"(W2[k * 32 + n]));
            if (nb < 2) g_wlo[s * 128 + l * 4 + q]       = tv;
            else        g_whi[s * 128 + l * 4 + (q - 4)] = tv;
        }
    }

    if (d < 16) s_x[tl][d] = x[t * 16 + d];
    __syncthreads();

    float ph = bp1[d];
    #pragma unroll
    for (int r = 0; r < 3; r++) ph += s_x[tl][13 + r] * Wp1[r * D + d];
    s_h[tl][d] = fmaxf(ph, 0.f);
    __syncthreads();

    float pos = bp2[d];
    #pragma unroll
    for (int k = 0; k < D; k++) pos += s_h[tl][k] * Wp2[k * D + d];
    float proj = bf[d] + pos;
    #pragma unroll
    for (int r = 0; r < 13; r++) proj += s_x[tl][r] * Wf[r * D + d];
    s_h2[tl][d] = proj;
    __syncthreads();

    float emb = bn[d];
    #pragma unroll
    for (int k = 0; k < D; k++) emb += s_h2[tl][k] * Wn[k * D + d];
    s_h[tl][d] = emb;
    __syncthreads();

    float av = b1[d];
    float bv = 0.f;
    #pragma unroll
    for (int k = 0; k < D; k++) {
        float e = s_h[tl][k];
        av += e * W1[k * D + d];
        bv += e * W1[(D + k) * D + d];
    }
    g_a[t * D + d] = av;
    g_b[t * D + d] = bv;
}

// ---------------------------------------------------------------------------
// Phase 2: persistent mma.sync tf32 kernel.
// CTA = 256 threads = 8 warps; tile = 4 i-rows x 32 j-cols = 128 pairs.
// Warp w: i-row ii = w>>1, j-halfblock jb = (w&1)*16.
// mma tile per warp: M=16 pairs (j = jb..jb+15 at fixed ii), N=32, K=64.
// A-fragments (h = relu(a_i + b_j), tf32) computed directly in registers.
// ---------------------------------------------------------------------------
#define NTILES 8192
#define GRID_PAIR 296
#define BSTR 68   // b_s/a_s row stride in words: 68 mod 32 = 4 -> conflict-free

__global__ void __launch_bounds__(256, 2)
pair_kernel(const float* __restrict__ b2, const float* __restrict__ W3,
            const float* __restrict__ b3, float* __restrict__ out)
{
    __shared__ float    a_s[4 * BSTR];
    __shared__ float    b_s[32 * BSTR];
    __shared__ uint32_t ws_lo[8 * 32 * 4];   // 4 KB
    __shared__ uint32_t ws_hi[8 * 32 * 4];   // 4 KB

    const int tid  = threadIdx.x;
    const int w    = tid >> 5;
    const int lane = tid & 31;
    const int gid  = lane >> 2;     // mma group 0..7
    const int t4   = lane & 3;      // thread-in-group
    const int ii   = w >> 1;        // i-row in tile
    const int jb   = (w & 1) * 16;  // j base in tile

    // ---- one-time: stage W2 fragments, preload b2/W3 cols, b3 ----
    {
        const uint4* lo4 = (const uint4*)g_wlo;
        const uint4* hi4 = (const uint4*)g_whi;
        ((uint4*)ws_lo)[tid] = lo4[tid];
        ((uint4*)ws_hi)[tid] = hi4[tid];
    }
    float b2c[8], w3c[8];
    #pragma unroll
    for (int nb = 0; nb < 4; nb++) {
        int c = 8 * nb + 2 * t4;
        b2c[2 * nb]     = __ldg(b2 + c);
        b2c[2 * nb + 1] = __ldg(b2 + c + 1);
        w3c[2 * nb]     = __ldg(W3 + c);
        w3c[2 * nb + 1] = __ldg(W3 + c + 1);
    }
    const float b3v = __ldg(b3);

    for (int t = blockIdx.x; t < NTILES; t += GRID_PAIR) {
        const int bb = t >> 11;
        const int r  = t & 2047;
        const int i0 = (r >> 4) * 4;
        const int j0 = (r & 15) * 32;

        __syncthreads();   // protect previous tile's b_s/a_s reads

        // ---- stage a (4x64) and b (32x64), coalesced float4 ----
        {
            const float4* gb4 = (const float4*)g_b;
            #pragma unroll
            for (int q = 0; q < 2; q++) {
                int idx = tid + 256 * q;          // 0..511
                int j = idx >> 4, c = idx & 15;
                float4 v = gb4[(bb * NSEQ + j0 + j) * 16 + c];
                *(float4*)&b_s[j * BSTR + c * 4] = v;
            }
            if (tid < 64) {
                const float4* ga4 = (const float4*)g_a;
                int i = tid >> 4, c = tid & 15;
                float4 v = ga4[(bb * NSEQ + i0 + i) * 16 + c];
                *(float4*)&a_s[i * BSTR + c * 4] = v;
            }
        }
        __syncthreads();

        // ---- mainloop: 8 k-steps of m16n8k8 tf32, N=32 ----
        float acc[16];
        #pragma unroll
        for (int n = 0; n < 16; n++) acc[n] = 0.f;

        const float* ap = &a_s[ii * BSTR + t4];
        const float* bp0 = &b_s[(jb + gid) * BSTR + t4];
        const float* bp1 = &b_s[(jb + gid + 8) * BSTR + t4];

        #pragma unroll
        for (int s = 0; s < 8; s++) {
            float av0 = ap[8 * s];
            float av1 = ap[8 * s + 4];
            float bv00 = bp0[8 * s], bv01 = bp0[8 * s + 4];
            float bv10 = bp1[8 * s], bv11 = bp1[8 * s + 4];

            uint32_t ra0, ra1, ra2, ra3;
            asm("cvt.rna.tf32.f32 %0, %1;" : "=r"(ra0) : "f"(fmaxf(av0 + bv00, 0.f)));
            asm("cvt.rna.tf32.f32 %0, %1;" : "=r"(ra1) : "f"(fmaxf(av0 + bv10, 0.f)));
            asm("cvt.rna.tf32.f32 %0, %1;" : "=r"(ra2) : "f"(fmaxf(av1 + bv01, 0.f)));
            asm("cvt.rna.tf32.f32 %0, %1;" : "=r"(ra3) : "f"(fmaxf(av1 + bv11, 0.f)));

            uint4 flo = *(const uint4*)&ws_lo[s * 128 + lane * 4];
            uint4 fhi = *(const uint4*)&ws_hi[s * 128 + lane * 4];

            asm volatile("mma.sync.aligned.m16n8k8.row.col.f32.tf32.tf32.f32 "
                "{%0,%1,%2,%3}, {%4,%5,%6,%7}, {%8,%9}, {%0,%1,%2,%3};"
                : "+f"(acc[0]), "+f"(acc[1]), "+f"(acc[2]), "+f"(acc[3])
                : "r"(ra0), "r"(ra1), "r"(ra2), "r"(ra3), "r"(flo.x), "r"(flo.y));
            asm volatile("mma.sync.aligned.m16n8k8.row.col.f32.tf32.tf32.f32 "
                "{%0,%1,%2,%3}, {%4,%5,%6,%7}, {%8,%9}, {%0,%1,%2,%3};"
                : "+f"(acc[4]), "+f"(acc[5]), "+f"(acc[6]), "+f"(acc[7])
                : "r"(ra0), "r"(ra1), "r"(ra2), "r"(ra3), "r"(flo.z), "r"(flo.w));
            asm volatile("mma.sync.aligned.m16n8k8.row.col.f32.tf32.tf32.f32 "
                "{%0,%1,%2,%3}, {%4,%5,%6,%7}, {%8,%9}, {%0,%1,%2,%3};"
                : "+f"(acc[8]), "+f"(acc[9]), "+f"(acc[10]), "+f"(acc[11])
                : "r"(ra0), "r"(ra1), "r"(ra2), "r"(ra3), "r"(fhi.x), "r"(fhi.y));
            asm volatile("mma.sync.aligned.m16n8k8.row.col.f32.tf32.tf32.f32 "
                "{%0,%1,%2,%3}, {%4,%5,%6,%7}, {%8,%9}, {%0,%1,%2,%3};"
                : "+f"(acc[12]), "+f"(acc[13]), "+f"(acc[14]), "+f"(acc[15])
                : "r"(ra0), "r"(ra1), "r"(ra2), "r"(ra3), "r"(fhi.z), "r"(fhi.w));
        }

        // ---- epilogue: relu(acc + b2) . W3, reduce across the 4-thread group
        //  c{0,1} -> pair row gid   (j = jb+gid),  cols 8nb+2t4, +1
        //  c{2,3} -> pair row gid+8 (j = jb+gid+8)
        float p0 = 0.f, p1 = 0.f;
        #pragma unroll
        for (int nb = 0; nb < 4; nb++) {
            p0 += fmaxf(acc[4 * nb]     + b2c[2 * nb],     0.f) * w3c[2 * nb]
                + fmaxf(acc[4 * nb + 1] + b2c[2 * nb + 1], 0.f) * w3c[2 * nb + 1];
            p1 += fmaxf(acc[4 * nb + 2] + b2c[2 * nb],     0.f) * w3c[2 * nb]
                + fmaxf(acc[4 * nb + 3] + b2c[2 * nb + 1], 0.f) * w3c[2 * nb + 1];
        }
        p0 += __shfl_xor_sync(0xffffffffu, p0, 1);
        p1 += __shfl_xor_sync(0xffffffffu, p1, 1);
        p0 += __shfl_xor_sync(0xffffffffu, p0, 2);
        p1 += __shfl_xor_sync(0xffffffffu, p1, 2);

        if (t4 == 0) {
            size_t ob = ((size_t)bb << 18) + (size_t)(i0 + ii) * NSEQ + j0 + jb;
            out[ob + gid]     = p0 + b3v;
            out[ob + gid + 8] = p1 + b3v;
        }
    }
}

// ---------------------------------------------------------------------------
extern "C" void kernel_launch(void* const* d_in, const int* in_sizes, int n_in,
                              void* d_out, int out_size)
{
    const float* x   = (const float*)d_in[0];
    const float* Wf  = (const float*)d_in[1];
    const float* bf  = (const float*)d_in[2];
    const float* Wp1 = (const float*)d_in[3];
    const float* bp1 = (const float*)d_in[4];
    const float* Wp2 = (const float*)d_in[5];
    const float* bp2 = (const float*)d_in[6];
    const float* Wn  = (const float*)d_in[7];
    const float* bn  = (const float*)d_in[8];
    const float* W1  = (const float*)d_in[9];
    const float* b1  = (const float*)d_in[10];
    const float* W2  = (const float*)d_in[11];
    const float* b2  = (const float*)d_in[12];
    const float* W3  = (const float*)d_in[13];
    const float* b3  = (const float*)d_in[14];
    float* out = (float*)d_out;

    precompute_kernel<<<N_TOK / 4, 256>>>(x, Wf, bf, Wp1, bp1, Wp2, bp2,
                                          Wn, bn, W1, b1, W2);
    pair_kernel<<<GRID_PAIR, 256>>>(b2, W3, b3, out);
}

// round 14
// speedup vs baseline: 1.0018x; 1.0018x over previous
#include <cuda_runtime.h>
#include <cstdint>

#define BATCH 4
#define NSEQ  512
#define N_TOK (BATCH * NSEQ)   // 2048
#define D     64

// Scratch (allocation-free rule: __device__ globals)
__device__ __align__(256) float    g_a[N_TOK * D];   // a = emb @ W1[:64] + b1
__device__ __align__(256) float    g_b[N_TOK * D];   // b = emb @ W1[64:]
// Per-lane tf32 B-fragments of W2 for mma.m16n8k8:
//   g_wlo[s][lane][q]: q = nb*2+r for nb=0,1 ; g_whi: nb=2,3
//   value = tf32( W2[ 8s + (lane&3) + 4r ][ 8nb + (lane>>2) ] )
__device__ __align__(256) uint32_t g_wlo[8 * 32 * 4];
__device__ __align__(256) uint32_t g_whi[8 * 32 * 4];

// ---------------------------------------------------------------------------
// Phase 1: per-token chain + W2 fragment repack
// ---------------------------------------------------------------------------
__global__ void precompute_kernel(
    const float* __restrict__ x,
    const float* __restrict__ Wf,  const float* __restrict__ bf,
    const float* __restrict__ Wp1, const float* __restrict__ bp1,
    const float* __restrict__ Wp2, const float* __restrict__ bp2,
    const float* __restrict__ Wn,  const float* __restrict__ bn,
    const float* __restrict__ W1,  const float* __restrict__ b1,
    const float* __restrict__ W2)
{
    __shared__ float s_x [4][16];
    __shared__ float s_h [4][D];
    __shared__ float s_h2[4][D];

    const int tl = threadIdx.x >> 6;
    const int d  = threadIdx.x & 63;
    const int t  = blockIdx.x * 4 + tl;

    if (blockIdx.x == 0) {
        // W2 [k=64][n=32] -> per-lane mma B fragments (tf32)
        for (int idx = threadIdx.x; idx < 2048; idx += 256) {
            int s  = idx >> 8;          // k-step 0..7
            int l  = (idx >> 3) & 31;   // lane
            int q  = idx & 7;           // 0..7
            int nb = q >> 1;            // n-block 0..3
            int r  = q & 1;             // b-reg 0..1
            int gid = l >> 2, t4 = l & 3;
            int k = 8 * s + t4 + 4 * r;
            int n = 8 * nb + gid;
            uint32_t tv;
            asm("cvt.rna.tf32.f32 %0, %1;" : "=r"(tv) : "f"(W2[k * 32 + n]));
            if (nb < 2) g_wlo[s * 128 + l * 4 + q]       = tv;
            else        g_whi[s * 128 + l * 4 + (q - 4)] = tv;
        }
    }

    if (d < 16) s_x[tl][d] = x[t * 16 + d];
    __syncthreads();

    float ph = bp1[d];
    #pragma unroll
    for (int r = 0; r < 3; r++) ph += s_x[tl][13 + r] * Wp1[r * D + d];
    s_h[tl][d] = fmaxf(ph, 0.f);
    __syncthreads();

    float pos = bp2[d];
    #pragma unroll
    for (int k = 0; k < D; k++) pos += s_h[tl][k] * Wp2[k * D + d];
    float proj = bf[d] + pos;
    #pragma unroll
    for (int r = 0; r < 13; r++) proj += s_x[tl][r] * Wf[r * D + d];
    s_h2[tl][d] = proj;
    __syncthreads();

    float emb = bn[d];
    #pragma unroll
    for (int k = 0; k < D; k++) emb += s_h2[tl][k] * Wn[k * D + d];
    s_h[tl][d] = emb;
    __syncthreads();

    float av = b1[d];
    float bv = 0.f;
    #pragma unroll
    for (int k = 0; k < D; k++) {
        float e = s_h[tl][k];
        av += e * W1[k * D + d];
        bv += e * W1[(D + k) * D + d];
    }
    g_a[t * D + d] = av;
    g_b[t * D + d] = bv;
}

// ---------------------------------------------------------------------------
// Phase 2: persistent mma.sync tf32 kernel.
// CTA = 256 threads = 8 warps; tile = 4 i-rows x 32 j-cols = 128 pairs.
// Warp w: i-row ii = w>>1, j-halfblock jb = (w&1)*16.
// mma tile per warp: M=16 pairs (j = jb..jb+15 at fixed ii), N=32, K=64.
// A-fragments (h = relu(a_i + b_j), tf32) computed directly in registers.
// ---------------------------------------------------------------------------
#define NTILES 8192
#define GRID_PAIR 296
#define BSTR 68   // b_s/a_s row stride in words: 68 mod 32 = 4 -> conflict-free

__global__ void __launch_bounds__(256, 2)
pair_kernel(const float* __restrict__ b2, const float* __restrict__ W3,
            const float* __restrict__ b3, float* __restrict__ out)
{
    __shared__ float    a_s[4 * BSTR];
    __shared__ float    b_s[32 * BSTR];
    __shared__ uint32_t ws_lo[8 * 32 * 4];   // 4 KB
    __shared__ uint32_t ws_hi[8 * 32 * 4];   // 4 KB

    const int tid  = threadIdx.x;
    const int w    = tid >> 5;
    const int lane = tid & 31;
    const int gid  = lane >> 2;     // mma group 0..7
    const int t4   = lane & 3;      // thread-in-group
    const int ii   = w >> 1;        // i-row in tile
    const int jb   = (w & 1) * 16;  // j base in tile

    // ---- one-time: stage W2 fragments, preload b2/W3 cols, b3 ----
    {
        const uint4* lo4 = (const uint4*)g_wlo;
        const uint4* hi4 = (const uint4*)g_whi;
        ((uint4*)ws_lo)[tid] = lo4[tid];
        ((uint4*)ws_hi)[tid] = hi4[tid];
    }
    float b2c[8], w3c[8];
    #pragma unroll
    for (int nb = 0; nb < 4; nb++) {
        int c = 8 * nb + 2 * t4;
        b2c[2 * nb]     = __ldg(b2 + c);
        b2c[2 * nb + 1] = __ldg(b2 + c + 1);
        w3c[2 * nb]     = __ldg(W3 + c);
        w3c[2 * nb + 1] = __ldg(W3 + c + 1);
    }
    const float b3v = __ldg(b3);

    for (int t = blockIdx.x; t < NTILES; t += GRID_PAIR) {
        const int bb = t >> 11;
        const int r  = t & 2047;
        const int i0 = (r >> 4) * 4;
        const int j0 = (r & 15) * 32;

        __syncthreads();   // protect previous tile's b_s/a_s reads

        // ---- stage a (4x64) and b (32x64), coalesced float4 ----
        {
            const float4* gb4 = (const float4*)g_b;
            #pragma unroll
            for (int q = 0; q < 2; q++) {
                int idx = tid + 256 * q;          // 0..511
                int j = idx >> 4, c = idx & 15;
                float4 v = gb4[(bb * NSEQ + j0 + j) * 16 + c];
                *(float4*)&b_s[j * BSTR + c * 4] = v;
            }
            if (tid < 64) {
                const float4* ga4 = (const float4*)g_a;
                int i = tid >> 4, c = tid & 15;
                float4 v = ga4[(bb * NSEQ + i0 + i) * 16 + c];
                *(float4*)&a_s[i * BSTR + c * 4] = v;
            }
        }
        __syncthreads();

        // ---- mainloop: 8 k-steps of m16n8k8 tf32, N=32 ----
        float acc[16];
        #pragma unroll
        for (int n = 0; n < 16; n++) acc[n] = 0.f;

        const float* ap = &a_s[ii * BSTR + t4];
        const float* bp0 = &b_s[(jb + gid) * BSTR + t4];
        const float* bp1 = &b_s[(jb + gid + 8) * BSTR + t4];

        #pragma unroll
        for (int s = 0; s < 8; s++) {
            float av0 = ap[8 * s];
            float av1 = ap[8 * s + 4];
            float bv00 = bp0[8 * s], bv01 = bp0[8 * s + 4];
            float bv10 = bp1[8 * s], bv11 = bp1[8 * s + 4];

            uint32_t ra0, ra1, ra2, ra3;
            asm("cvt.rna.tf32.f32 %0, %1;" : "=r"(ra0) : "f"(fmaxf(av0 + bv00, 0.f)));
            asm("cvt.rna.tf32.f32 %0, %1;" : "=r"(ra1) : "f"(fmaxf(av0 + bv10, 0.f)));
            asm("cvt.rna.tf32.f32 %0, %1;" : "=r"(ra2) : "f"(fmaxf(av1 + bv01, 0.f)));
            asm("cvt.rna.tf32.f32 %0, %1;" : "=r"(ra3) : "f"(fmaxf(av1 + bv11, 0.f)));

            uint4 flo = *(const uint4*)&ws_lo[s * 128 + lane * 4];
            uint4 fhi = *(const uint4*)&ws_hi[s * 128 + lane * 4];

            asm volatile("mma.sync.aligned.m16n8k8.row.col.f32.tf32.tf32.f32 "
                "{%0,%1,%2,%3}, {%4,%5,%6,%7}, {%8,%9}, {%0,%1,%2,%3};"
                : "+f"(acc[0]), "+f"(acc[1]), "+f"(acc[2]), "+f"(acc[3])
                : "r"(ra0), "r"(ra1), "r"(ra2), "r"(ra3), "r"(flo.x), "r"(flo.y));
            asm volatile("mma.sync.aligned.m16n8k8.row.col.f32.tf32.tf32.f32 "
                "{%0,%1,%2,%3}, {%4,%5,%6,%7}, {%8,%9}, {%0,%1,%2,%3};"
                : "+f"(acc[4]), "+f"(acc[5]), "+f"(acc[6]), "+f"(acc[7])
                : "r"(ra0), "r"(ra1), "r"(ra2), "r"(ra3), "r"(flo.z), "r"(flo.w));
            asm volatile("mma.sync.aligned.m16n8k8.row.col.f32.tf32.tf32.f32 "
                "{%0,%1,%2,%3}, {%4,%5,%6,%7}, {%8,%9}, {%0,%1,%2,%3};"
                : "+f"(acc[8]), "+f"(acc[9]), "+f"(acc[10]), "+f"(acc[11])
                : "r"(ra0), "r"(ra1), "r"(ra2), "r"(ra3), "r"(fhi.x), "r"(fhi.y));
            asm volatile("mma.sync.aligned.m16n8k8.row.col.f32.tf32.tf32.f32 "
                "{%0,%1,%2,%3}, {%4,%5,%6,%7}, {%8,%9}, {%0,%1,%2,%3};"
                : "+f"(acc[12]), "+f"(acc[13]), "+f"(acc[14]), "+f"(acc[15])
                : "r"(ra0), "r"(ra1), "r"(ra2), "r"(ra3), "r"(fhi.z), "r"(fhi.w));
        }

        // ---- epilogue: relu(acc + b2) . W3, reduce across the 4-thread group
        //  c{0,1} -> pair row gid   (j = jb+gid),  cols 8nb+2t4, +1
        //  c{2,3} -> pair row gid+8 (j = jb+gid+8)
        float p0 = 0.f, p1 = 0.f;
        #pragma unroll
        for (int nb = 0; nb < 4; nb++) {
            p0 += fmaxf(acc[4 * nb]     + b2c[2 * nb],     0.f) * w3c[2 * nb]
                + fmaxf(acc[4 * nb + 1] + b2c[2 * nb + 1], 0.f) * w3c[2 * nb + 1];
            p1 += fmaxf(acc[4 * nb + 2] + b2c[2 * nb],     0.f) * w3c[2 * nb]
                + fmaxf(acc[4 * nb + 3] + b2c[2 * nb + 1], 0.f) * w3c[2 * nb + 1];
        }
        p0 += __shfl_xor_sync(0xffffffffu, p0, 1);
        p1 += __shfl_xor_sync(0xffffffffu, p1, 1);
        p0 += __shfl_xor_sync(0xffffffffu, p0, 2);
        p1 += __shfl_xor_sync(0xffffffffu, p1, 2);

        if (t4 == 0) {
            size_t ob = ((size_t)bb << 18) + (size_t)(i0 + ii) * NSEQ + j0 + jb;
            out[ob + gid]     = p0 + b3v;
            out[ob + gid + 8] = p1 + b3v;
        }
    }
}

// ---------------------------------------------------------------------------
extern "C" void kernel_launch(void* const* d_in, const int* in_sizes, int n_in,
                              void* d_out, int out_size)
{
    const float* x   = (const float*)d_in[0];
    const float* Wf  = (const float*)d_in[1];
    const float* bf  = (const float*)d_in[2];
    const float* Wp1 = (const float*)d_in[3];
    const float* bp1 = (const float*)d_in[4];
    const float* Wp2 = (const float*)d_in[5];
    const float* bp2 = (const float*)d_in[6];
    const float* Wn  = (const float*)d_in[7];
    const float* bn  = (const float*)d_in[8];
    const float* W1  = (const float*)d_in[9];
    const float* b1  = (const float*)d_in[10];
    const float* W2  = (const float*)d_in[11];
    const float* b2  = (const float*)d_in[12];
    const float* W3  = (const float*)d_in[13];
    const float* b3  = (const float*)d_in[14];
    float* out = (float*)d_out;

    precompute_kernel<<<N_TOK / 4, 256>>>(x, Wf, bf, Wp1, bp1, Wp2, bp2,
                                          Wn, bn, W1, b1, W2);
    pair_kernel<<<GRID_PAIR, 256>>>(b2, W3, b3, out);
}